// round 12
// baseline (speedup 1.0000x reference)
#include <cuda_runtime.h>
#include <cuda_fp16.h>
#include <math.h>
#include <stdint.h>

// Problem constants
#define B   256
#define Hd  1024
#define L   400
#define V   50257
#define NTV 393              // ceil(V/128)

#define OUT_H    ((long)B * V)
#define OUT_AW   ((long)B * V + (long)B * Hd)

// ---------------- scratch (device globals) ---------------------------------
__device__ float g_scores[B * L];
__device__ float g_attn[B * Hd];
__device__ float g_o[B * Hd];
__device__ float g_part[4L * B * 3 * Hd];     // split-K partials [4][B][3H]
__device__ float g_rsum[(long)B * NTV];       // [row][tile] exp-sums
__device__ float g_lse[B];
__device__ __half g_w16[(long)V * Hd];        // fp16 out_W (103 MB)
__device__ __half g_h16[B * Hd];              // fp16 h_new

// ---------------- helpers ---------------------------------------------------
__device__ __forceinline__ uint32_t smem_u32(const void* p) {
    uint32_t a;
    asm("{ .reg .u64 t; cvta.to.shared.u64 t, %1; cvt.u32.u64 %0, t; }" : "=r"(a) : "l"(p));
    return a;
}

__device__ __forceinline__ uint32_t h2bits(float x, float y) {
    __half2 h = __floats2half2_rn(x, y);
    return *(uint32_t*)&h;
}

#define SWZ128(x) ((x) ^ (((x) >> 3) & 0x70))
#define SWZ64(x)  ((x) ^ (((x) >> 3) & 0x30))

__device__ __forceinline__ void ldsm_x4(uint32_t* r, uint32_t addr) {
    asm volatile("ldmatrix.sync.aligned.m8n8.x4.shared.b16 {%0,%1,%2,%3}, [%4];"
                 : "=r"(r[0]), "=r"(r[1]), "=r"(r[2]), "=r"(r[3]) : "r"(addr));
}

__device__ __forceinline__ void mma_f16(float* c, const uint32_t* a, const uint32_t* b) {
    asm volatile(
        "mma.sync.aligned.m16n8k16.row.col.f32.f16.f16.f32 "
        "{%0,%1,%2,%3}, {%4,%5,%6,%7}, {%8,%9}, {%0,%1,%2,%3};"
        : "+f"(c[0]), "+f"(c[1]), "+f"(c[2]), "+f"(c[3])
        : "r"(a[0]), "r"(a[1]), "r"(a[2]), "r"(a[3]), "r"(b[0]), "r"(b[1]));
}

// fast exp (full-rate FFMA path)
__device__ __forceinline__ float fexp(float x)
{
    float t = fmaxf(x * 1.44269504f, -125.0f);
    float fi = t + 12582912.f;
    int   i = __float_as_int(fi);
    float fr = t - (fi - 12582912.f);
    float y = fr * 0.69314718f;
    float p = fmaf(y, 0.25f, 1.f);
    p = fmaf(y * p, 0.33333333f, 1.f);
    p = fmaf(y * p, 0.5f, 1.f);
    p = fmaf(y, p, 1.f);
    return __int_as_float((i + (127 - 0x4B400000)) << 23) * p;
}

// ---------------- fp32→fp16 convert (8 elems/thread) -------------------------
__global__ void f2h_vec(const float* __restrict__ in, __half* __restrict__ out, long n)
{
    long i = ((long)blockIdx.x * blockDim.x + threadIdx.x) * 8;
    if (i >= n) return;
    float4 a = *(const float4*)(in + i);
    float4 b = *(const float4*)(in + i + 4);
    uint4 u;
    u.x = h2bits(a.x, a.y); u.y = h2bits(a.z, a.w);
    u.z = h2bits(b.x, b.y); u.w = h2bits(b.z, b.w);
    *(uint4*)(out + i) = u;
}

// ---------------- cp.async fp16 logits GEMM ---------------------------------
// out_logp[256,V] = h16[256,1024] @ w16[V,1024]^T + bias; fused exp-sums.
// grid (NTV, 2), 256 thr, BK=32, 6 stages x 16KB (A 8KB + B 8KB), SW64,
// wait_group 4 -> 4 chunks of prefetch in flight (covers DRAM latency).
#define LG_STAGES 6
#define LG_SMEM (LG_STAGES * 16384)

__global__ __launch_bounds__(256, 2) void gemm_lg(
    const __half* __restrict__ A16, const __half* __restrict__ W16,
    const float* __restrict__ bias, float* __restrict__ C,
    float* __restrict__ rsum)
{
    extern __shared__ char smem[];
    const uint32_t sb = smem_u32(smem);
    const int N = V, K = Hd;

    const int t = threadIdx.x;
    const int lane = t & 31;
    const int wid = t >> 5;
    const int wm = wid >> 2;       // 0..1
    const int wn = wid & 3;        // 0..3
    const int g = lane >> 2;
    const int q = lane & 3;

    const int m0 = blockIdx.y * 128;
    const int n0 = blockIdx.x * 128;

    const int lrow = t >> 2;            // 0..63 (+64)
    const int lc16 = (t & 3) * 16;      // byte col in 64B row
    const int lc8  = (t & 3) * 8;       // half col

    float acc[4][4][4];
    #pragma unroll
    for (int i = 0; i < 4; i++)
        #pragma unroll
        for (int j = 0; j < 4; j++)
            #pragma unroll
            for (int v = 0; v < 4; v++) acc[i][j][v] = 0.f;

    auto issue_stage = [&](int s, int c) {
        const int k0 = c * 32;
        const uint32_t Ab = sb + s * 16384;
        const uint32_t Bb = Ab + 8192;
        #pragma unroll
        for (int i = 0; i < 2; i++) {
            int row = lrow + i * 64;
            const __half* src = A16 + (long)(m0 + row) * K + k0 + lc8;
            uint32_t dst = Ab + SWZ64((uint32_t)(row * 64 + lc16));
            asm volatile("cp.async.cg.shared.global [%0], [%1], 16;" :: "r"(dst), "l"(src));
        }
        #pragma unroll
        for (int i = 0; i < 2; i++) {
            int row = lrow + i * 64;
            int n = n0 + row;
            const __half* src = W16 + (long)n * K + k0 + lc8;
            uint32_t dst = Bb + SWZ64((uint32_t)(row * 64 + lc16));
            int bytes = (n < N) ? 16 : 0;
            asm volatile("cp.async.cg.shared.global [%0], [%1], 16, %2;"
                         :: "r"(dst), "l"(src), "r"(bytes));
        }
        asm volatile("cp.async.commit_group;" ::: "memory");
    };

    const int a_row = lane & 15;
    const int a_cb = (lane >> 4) << 4;
    const int b_row = (lane & 7) + ((lane >> 4) << 3);
    const int b_cb = ((lane >> 3) & 1) << 4;

    auto compute = [&](int s) {
        const uint32_t Ab = sb + s * 16384;
        const uint32_t Bb = Ab + 8192;
        #pragma unroll
        for (int ks = 0; ks < 2; ks++) {
            uint32_t af[4][4], bf[2][4];
            #pragma unroll
            for (int mt = 0; mt < 4; mt++) {
                int r = wm * 64 + mt * 16 + a_row;
                ldsm_x4(af[mt], Ab + SWZ64((uint32_t)(r * 64 + ks * 32 + a_cb)));
            }
            #pragma unroll
            for (int np = 0; np < 2; np++) {
                int r = wn * 32 + np * 16 + b_row;
                ldsm_x4(bf[np], Bb + SWZ64((uint32_t)(r * 64 + ks * 32 + b_cb)));
            }
            #pragma unroll
            for (int mt = 0; mt < 4; mt++)
                #pragma unroll
                for (int nt = 0; nt < 4; nt++)
                    mma_f16(acc[mt][nt], af[mt], &bf[nt >> 1][(nt & 1) * 2]);
        }
    };

    const int NCH = K / 32;   // 32
    #pragma unroll
    for (int s = 0; s < LG_STAGES - 1; s++) issue_stage(s, s);
    int s = 0;
    for (int c = 0; c < NCH; c++) {
        asm volatile("cp.async.wait_group %0;" :: "n"(LG_STAGES - 2) : "memory");
        __syncthreads();
        compute(s);
        if (c + LG_STAGES - 1 < NCH) issue_stage((s + LG_STAGES - 1) % LG_STAGES, c + LG_STAGES - 1);
        else asm volatile("cp.async.commit_group;" ::: "memory");
        if (++s == LG_STAGES) s = 0;
    }

    // ---- epilogue: bias + store + bare exp-sum ----
    float se[4][2];
    #pragma unroll
    for (int mt = 0; mt < 4; mt++) { se[mt][0] = 0.f; se[mt][1] = 0.f; }
    #pragma unroll
    for (int mt = 0; mt < 4; mt++) {
        int row = m0 + wm * 64 + mt * 16 + g;
        #pragma unroll
        for (int nt = 0; nt < 4; nt++) {
            int col = n0 + wn * 32 + nt * 8 + 2 * q;
            float b0 = (col < N) ? bias[col] : 0.f;
            float b1 = (col + 1 < N) ? bias[col + 1] : 0.f;
            float v0 = acc[mt][nt][0] + b0, v1 = acc[mt][nt][1] + b1;
            float v2 = acc[mt][nt][2] + b0, v3 = acc[mt][nt][3] + b1;
            if (col < N)     { C[(long)row * N + col]           = v0; se[mt][0] += fexp(v0); }
            if (col + 1 < N) { C[(long)row * N + col + 1]       = v1; se[mt][0] += fexp(v1); }
            if (col < N)     { C[(long)(row + 8) * N + col]     = v2; se[mt][1] += fexp(v2); }
            if (col + 1 < N) { C[(long)(row + 8) * N + col + 1] = v3; se[mt][1] += fexp(v3); }
        }
    }
    float* reds = (float*)smem;
    __syncthreads();
    #pragma unroll
    for (int mt = 0; mt < 4; mt++) {
        #pragma unroll
        for (int half = 0; half < 2; half++) {
            float sv = se[mt][half];
            sv += __shfl_xor_sync(0xffffffff, sv, 1);
            sv += __shfl_xor_sync(0xffffffff, sv, 2);
            if (q == 0) {
                int rloc = wm * 64 + mt * 16 + g + half * 8;
                reds[wn * 128 + rloc] = sv;
            }
        }
    }
    __syncthreads();
    if (t < 128) {
        float sm = reds[t] + reds[128 + t] + reds[256 + t] + reds[384 + t];
        rsum[(long)(m0 + t) * NTV + blockIdx.x] = sm;
    }
}

// ---------------- fp16 tensor-core GEMM (R9 engine, small GEMMs) ------------
#define GH_SMEM 65536

template<int TRANSB, int CONCAT>
__global__ __launch_bounds__(256, 1) void gemm_h16(
    const float* __restrict__ A1, const float* __restrict__ A2, int KA1,
    const float* __restrict__ W,
    float* __restrict__ C, int N, int K, int chunkK)
{
    extern __shared__ char smem[];
    const uint32_t sb = smem_u32(smem);

    const int t = threadIdx.x;
    const int lane = t & 31;
    const int wid = t >> 5;
    const int wm = wid >> 2;
    const int wn = wid & 3;
    const int g = lane >> 2;
    const int q = lane & 3;

    const int m0 = blockIdx.y * 128;
    const int n0 = blockIdx.x * 128;
    const int kstart = blockIdx.z * chunkK;
    const int kend = min(kstart + chunkK, K);
    const int KA2 = K - KA1;

    const int arow = t >> 4;
    const int acol = (t & 15) * 4;

    float4 ra[8], rb[8];
    float4 rba[4], rbb[4];

    float acc[4][4][4];
    #pragma unroll
    for (int i = 0; i < 4; i++)
        #pragma unroll
        for (int j = 0; j < 4; j++)
            #pragma unroll
            for (int v = 0; v < 4; v++) acc[i][j][v] = 0.f;

    auto loadA = [&](int k0) {
        #pragma unroll
        for (int i = 0; i < 8; i++) {
            int m = m0 + arow + 16 * i;
            int k = k0 + acol;
            ra[i] = make_float4(0.f, 0.f, 0.f, 0.f);
            if (k < kend) {
                if constexpr (CONCAT) {
                    if (k < KA1) ra[i] = *(const float4*)&A1[(long)m * KA1 + k];
                    else         ra[i] = *(const float4*)&A2[(long)m * KA2 + (k - KA1)];
                } else {
                    ra[i] = *(const float4*)&A1[(long)m * K + k];
                }
            }
        }
    };
    auto loadB = [&](int k0) {
        if (TRANSB) {
            #pragma unroll
            for (int i = 0; i < 8; i++) {
                int n = n0 + arow + 16 * i;
                int k = k0 + acol;
                rb[i] = make_float4(0.f, 0.f, 0.f, 0.f);
                if (n < N && k < kend) rb[i] = *(const float4*)&W[(long)n * K + k];
            }
        } else {
            #pragma unroll
            for (int i = 0; i < 4; i++) {
                int cell = t + i * 256;
                int kp = cell >> 5;
                int nq = cell & 31;
                int k = k0 + 2 * kp;
                int n = n0 + nq * 4;
                rba[i] = make_float4(0.f, 0.f, 0.f, 0.f);
                rbb[i] = make_float4(0.f, 0.f, 0.f, 0.f);
                if (k < kend && n < N) {
                    rba[i] = *(const float4*)&W[(long)k * N + n];
                    if (k + 1 < kend) rbb[i] = *(const float4*)&W[(long)(k + 1) * N + n];
                }
            }
        }
    };
    auto storeAB = [&](int s) {
        char* Ab = smem + s * 32768;
        char* Bb = smem + s * 32768 + 16384;
        #pragma unroll
        for (int i = 0; i < 8; i++) {
            int row = arow + 16 * i;
            uint32_t off = SWZ128((uint32_t)(row * 128 + acol * 2));
            *(uint2*)(Ab + off) = make_uint2(h2bits(ra[i].x, ra[i].y), h2bits(ra[i].z, ra[i].w));
        }
        if (TRANSB) {
            #pragma unroll
            for (int i = 0; i < 8; i++) {
                int row = arow + 16 * i;
                uint32_t off = SWZ128((uint32_t)(row * 128 + acol * 2));
                *(uint2*)(Bb + off) = make_uint2(h2bits(rb[i].x, rb[i].y), h2bits(rb[i].z, rb[i].w));
            }
        } else {
            #pragma unroll
            for (int i = 0; i < 4; i++) {
                int cell = t + i * 256;
                int kp = cell >> 5;
                int nq = cell & 31;
                const float* fa = (const float*)&rba[i];
                const float* fb = (const float*)&rbb[i];
                #pragma unroll
                for (int j = 0; j < 4; j++) {
                    int row = nq * 4 + j;
                    uint32_t off = SWZ128((uint32_t)(row * 128 + kp * 4));
                    *(uint32_t*)(Bb + off) = h2bits(fa[j], fb[j]);
                }
            }
        }
    };

    const int a_row = lane & 15;
    const int a_cb = (lane >> 4) << 4;
    const int b_row = (lane & 7) + ((lane >> 4) << 3);
    const int b_cb = ((lane >> 3) & 1) << 4;

    auto compute = [&](int s) {
        const uint32_t Ab = sb + s * 32768;
        const uint32_t Bb = Ab + 16384;
        #pragma unroll
        for (int ks = 0; ks < 4; ks++) {
            uint32_t af[4][4], bf[2][4];
            #pragma unroll
            for (int mt = 0; mt < 4; mt++) {
                int r = wm * 64 + mt * 16 + a_row;
                ldsm_x4(af[mt], Ab + SWZ128((uint32_t)(r * 128 + ks * 32 + a_cb)));
            }
            #pragma unroll
            for (int np = 0; np < 2; np++) {
                int r = wn * 32 + np * 16 + b_row;
                ldsm_x4(bf[np], Bb + SWZ128((uint32_t)(r * 128 + ks * 32 + b_cb)));
            }
            #pragma unroll
            for (int mt = 0; mt < 4; mt++)
                #pragma unroll
                for (int nt = 0; nt < 4; nt++)
                    mma_f16(acc[mt][nt], af[mt], &bf[nt >> 1][(nt & 1) * 2]);
        }
    };

    const int ntiles = (kend - kstart + 63) / 64;

    loadA(kstart); loadB(kstart);
    storeAB(0);
    __syncthreads();
    for (int c = 1; c < ntiles; c++) {
        loadA(kstart + c * 64); loadB(kstart + c * 64);
        compute((c - 1) & 1);
        storeAB(c & 1);
        __syncthreads();
    }
    compute((ntiles - 1) & 1);

    float* Cw = C + (long)blockIdx.z * 256 * N;
    #pragma unroll
    for (int mt = 0; mt < 4; mt++) {
        int row = m0 + wm * 64 + mt * 16 + g;
        #pragma unroll
        for (int nt = 0; nt < 4; nt++) {
            int col = n0 + wn * 32 + nt * 8 + 2 * q;
            if (col < N)     Cw[(long)row * N + col]           = acc[mt][nt][0];
            if (col + 1 < N) Cw[(long)row * N + col + 1]       = acc[mt][nt][1];
            if (col < N)     Cw[(long)(row + 8) * N + col]     = acc[mt][nt][2];
            if (col + 1 < N) Cw[(long)(row + 8) * N + col + 1] = acc[mt][nt][3];
        }
    }
}

// ---------------- split-K reduce (+bias, +relu) — deterministic -------------
__global__ void reduce_bias(const float* __restrict__ part, const float* __restrict__ bias,
                            float* __restrict__ out, int MN, int N, int SK, int relu)
{
    int idx = blockIdx.x * blockDim.x + threadIdx.x;
    if (idx >= MN) return;
    float s = 0.f;
    for (int c = 0; c < SK; c++) s += part[(long)c * MN + idx];
    if (bias) s += bias[idx % N];
    if (relu) s = fmaxf(s, 0.f);
    out[idx] = s;
}

// ---------------- fused GRU: reduce + gates + dual fp32/fp16 h write --------
__global__ void gru_fuse(const float* __restrict__ part, const float* __restrict__ hidden,
                         const float* __restrict__ bih, const float* __restrict__ bhh,
                         float* __restrict__ h_new, __half* __restrict__ h16)
{
    int idx = blockIdx.x * blockDim.x + threadIdx.x;
    if (idx >= B * Hd) return;
    int b = idx / Hd, j = idx - b * Hd;
    const long NN = 3 * Hd;
    const long MN = (long)B * NN;
    const float* giA = part;
    const float* ghA = part + 2 * MN;
    long base = (long)b * NN + j;

    float ir = giA[base] + giA[MN + base] + bih[j];
    float iz = giA[base + Hd] + giA[MN + base + Hd] + bih[j + Hd];
    float in_ = giA[base + 2 * Hd] + giA[MN + base + 2 * Hd] + bih[j + 2 * Hd];
    float hr = ghA[base] + ghA[MN + base] + bhh[j];
    float hz = ghA[base + Hd] + ghA[MN + base + Hd] + bhh[j + Hd];
    float hn = ghA[base + 2 * Hd] + ghA[MN + base + 2 * Hd] + bhh[j + 2 * Hd];

    float r = 1.f / (1.f + expf(-(ir + hr)));
    float z = 1.f / (1.f + expf(-(iz + hz)));
    float nn = tanhf(in_ + r * hn);
    float h = (1.f - z) * nn + z * hidden[idx];
    h_new[idx] = h;
    h16[idx] = __float2half_rn(h);
}

// ---------------- fused split-K reduce + bias + softmax (scores) -------------
// warp per row; reads SK=8 partials [z][row][L] + bias, softmax -> out
__global__ void softmax_red(const float* __restrict__ part, const float* __restrict__ bias,
                            float* __restrict__ out, int n)
{
    int w = (blockIdx.x * blockDim.x + threadIdx.x) >> 5;
    int lid = threadIdx.x & 31;
    if (w >= B) return;
    float* y = out + (long)w * n;

    float vals[13];   // ceil(400/32) = 13
    float m = -1e30f;
    int nv = 0;
    for (int i = lid; i < n; i += 32, nv++) {
        float s = bias[i];
        #pragma unroll
        for (int c = 0; c < 8; c++) s += part[(long)c * B * L + (long)w * n + i];
        vals[nv] = s;
        m = fmaxf(m, s);
    }
    #pragma unroll
    for (int o = 16; o > 0; o >>= 1) m = fmaxf(m, __shfl_xor_sync(0xffffffff, m, o));
    float s = 0.f;
    for (int v = 0; v < nv; v++) { vals[v] = fexp(vals[v] - m); s += vals[v]; }
    #pragma unroll
    for (int o = 16; o > 0; o >>= 1) s += __shfl_xor_sync(0xffffffff, s, o);
    float inv = 1.f / s;
    int v = 0;
    for (int i = lid; i < n; i += 32, v++) y[i] = vals[v] * inv;
}

// ---------------- parallel lse: one block per row, plain sum -----------------
__global__ void lse_reduce(const float* __restrict__ rsum, float* __restrict__ lse)
{
    int row = blockIdx.x;
    int t = threadIdx.x;   // 128
    float s = 0.f;
    for (int tile = t; tile < NTV; tile += 128) s += rsum[(long)row * NTV + tile];
    #pragma unroll
    for (int o = 16; o > 0; o >>= 1) s += __shfl_xor_sync(0xffffffff, s, o);
    __shared__ float ss[4];
    if ((t & 31) == 0) ss[t >> 5] = s;
    __syncthreads();
    if (t == 0) lse[row] = logf(ss[0] + ss[1] + ss[2] + ss[3]);
}

// ---------------- final: logp -= lse (in place) ------------------------------
__global__ void logp_sub(float* __restrict__ logp, const float* __restrict__ lse)
{
    int col = blockIdx.x * 1024 + threadIdx.x;
    int row = blockIdx.y;
    if (col < V) logp[(long)row * V + col] -= lse[row];
}

// ---------------- launch -----------------------------------------------------
extern "C" void kernel_launch(void* const* d_in, const int* in_sizes, int n_in,
                              void* d_out, int out_size)
{
    const float* embedded = (const float*)d_in[0];
    const float* hidden   = (const float*)d_in[1];
    const float* enc      = (const float*)d_in[2];
    const float* attn_W   = (const float*)d_in[3];
    const float* attn_b   = (const float*)d_in[4];
    const float* comb_W   = (const float*)d_in[5];
    const float* comb_b   = (const float*)d_in[6];
    const float* gru_Wih  = (const float*)d_in[7];
    const float* gru_Whh  = (const float*)d_in[8];
    const float* gru_bih  = (const float*)d_in[9];
    const float* gru_bhh  = (const float*)d_in[10];
    const float* out_W    = (const float*)d_in[11];
    const float* out_b    = (const float*)d_in[12];

    float* out = (float*)d_out;
    float* out_logp = out;
    float* out_h    = out + OUT_H;
    float* out_aw   = out + OUT_AW;

    float *scores, *attn, *o, *part, *rsum, *lse;
    __half *w16, *h16;
    cudaGetSymbolAddress((void**)&scores, g_scores);
    cudaGetSymbolAddress((void**)&attn, g_attn);
    cudaGetSymbolAddress((void**)&o, g_o);
    cudaGetSymbolAddress((void**)&part, g_part);
    cudaGetSymbolAddress((void**)&rsum, g_rsum);
    cudaGetSymbolAddress((void**)&lse, g_lse);
    cudaGetSymbolAddress((void**)&w16, g_w16);
    cudaGetSymbolAddress((void**)&h16, g_h16);

    static cudaStream_t sW = nullptr, sG = nullptr;
    static cudaEvent_t evFork, evW, evG;
    if (sW == nullptr) {
        cudaStreamCreateWithFlags(&sW, cudaStreamNonBlocking);
        cudaStreamCreateWithFlags(&sG, cudaStreamNonBlocking);
        cudaEventCreateWithFlags(&evFork, cudaEventDisableTiming);
        cudaEventCreateWithFlags(&evW, cudaEventDisableTiming);
        cudaEventCreateWithFlags(&evG, cudaEventDisableTiming);
    }

    cudaFuncSetAttribute((const void*)gemm_h16<1, 1>, cudaFuncAttributeMaxDynamicSharedMemorySize, GH_SMEM);
    cudaFuncSetAttribute((const void*)gemm_h16<1, 0>, cudaFuncAttributeMaxDynamicSharedMemorySize, GH_SMEM);
    cudaFuncSetAttribute((const void*)gemm_h16<0, 0>, cudaFuncAttributeMaxDynamicSharedMemorySize, GH_SMEM);
    cudaFuncSetAttribute((const void*)gemm_lg, cudaFuncAttributeMaxDynamicSharedMemorySize, LG_SMEM);

    // ---- fork: out_W conversion (stream sW) + gh GEMM (stream sG) ----
    cudaEventRecord(evFork, 0);

    cudaStreamWaitEvent(sW, evFork, 0);
    f2h_vec<<<(int)(((long)V * Hd / 8 + 255) / 256), 256, 0, sW>>>(out_W, w16, (long)V * Hd);
    cudaEventRecord(evW, sW);

    cudaStreamWaitEvent(sG, evFork, 0);
    gemm_h16<1, 0><<<dim3(24, 2, 2), 256, GH_SMEM, sG>>>(hidden, nullptr, Hd, gru_Whh,
                                                         part + 2L * B * 3 * Hd, 3 * Hd, Hd, 512);
    cudaEventRecord(evG, sG);

    // ---- main chain (legacy stream) ----
    // 1. scores partials = [x|h] @ attn_W^T, split-K=8
    gemm_h16<1, 1><<<dim3(4, 2, 8), 256, GH_SMEM>>>(embedded, hidden, Hd, attn_W,
                                                    part, L, 2 * Hd, 256);

    // 2. fused reduce+bias+softmax -> out_aw
    softmax_red<<<32, 256>>>(part, attn_b, out_aw, L);

    // 3. attn_applied = attn_weights @ enc (NN), split-K=4
    gemm_h16<0, 0><<<dim3(8, 2, 4), 256, GH_SMEM>>>(out_aw, nullptr, L, enc,
                                                    part, Hd, L, 128);
    reduce_bias<<<(B * Hd + 255) / 256, 256>>>(part, nullptr, attn, B * Hd, Hd, 4, 0);

    // 4. o = relu([x|attn] @ comb_W^T + comb_b), split-K=4
    gemm_h16<1, 1><<<dim3(8, 2, 4), 256, GH_SMEM>>>(embedded, attn, Hd, comb_W,
                                                    part, Hd, 2 * Hd, 512);
    reduce_bias<<<(B * Hd + 255) / 256, 256>>>(part, comb_b, o, B * Hd, Hd, 4, 1);

    // 5. gi = o @ Wih^T split-K=2; join gh; fused gates + fp16 h
    gemm_h16<1, 0><<<dim3(24, 2, 2), 256, GH_SMEM>>>(o, nullptr, Hd, gru_Wih,
                                                     part, 3 * Hd, Hd, 512);
    cudaStreamWaitEvent(0, evG, 0);
    gru_fuse<<<(B * Hd + 255) / 256, 256>>>(part, hidden, gru_bih, gru_bhh, out_h, h16);

    // 6. join w16; logits -> out_logp, deep cp.async pipeline, exp-sum fused
    cudaStreamWaitEvent(0, evW, 0);
    gemm_lg<<<dim3(NTV, 2), 256, LG_SMEM>>>(h16, w16, out_b, out_logp, rsum);

    // 7. lse + in-place subtract
    lse_reduce<<<B, 128>>>(rsum, lse);
    logp_sub<<<dim3(50, B), 1024>>>(out_logp, lse);
}

// round 13
// speedup vs baseline: 1.1410x; 1.1410x over previous
#include <cuda_runtime.h>
#include <cuda_fp16.h>
#include <math.h>
#include <stdint.h>

// Problem constants
#define B   256
#define Hd  1024
#define L   400
#define V   50257
#define NTV 393              // ceil(V/128)

#define OUT_H    ((long)B * V)
#define OUT_AW   ((long)B * V + (long)B * Hd)

// ---------------- scratch (device globals) ---------------------------------
__device__ float g_scores[B * L];
__device__ float g_attn[B * Hd];
__device__ float g_o[B * Hd];
__device__ float g_part[6L * B * 3 * Hd];     // split-K partials: gi [0,3MN), gh [3MN,6MN)
__device__ float g_rsum[(long)B * NTV];       // [row][tile] exp-sums
__device__ __half g_w16[(long)V * Hd];        // fp16 out_W
__device__ __half g_h16[B * Hd];              // fp16 h_new
__device__ __half g_h16in[B * Hd];            // fp16 hidden (input)
__device__ __half g_x16[B * Hd];              // fp16 embedded
__device__ __half g_attn16[B * Hd];           // fp16 attn_applied
__device__ __half g_o16[B * Hd];              // fp16 o
__device__ __half g_whh16[3 * Hd * Hd];
__device__ __half g_wih16[3 * Hd * Hd];
__device__ __half g_combW16[Hd * 2 * Hd];

// ---------------- helpers ---------------------------------------------------
__device__ __forceinline__ uint32_t smem_u32(const void* p) {
    uint32_t a;
    asm("{ .reg .u64 t; cvta.to.shared.u64 t, %1; cvt.u32.u64 %0, t; }" : "=r"(a) : "l"(p));
    return a;
}

__device__ __forceinline__ uint32_t h2bits(float x, float y) {
    __half2 h = __floats2half2_rn(x, y);
    return *(uint32_t*)&h;
}

#define SWZ128(x) ((x) ^ (((x) >> 3) & 0x70))
#define SWZ64(x)  ((x) ^ (((x) >> 3) & 0x30))

__device__ __forceinline__ void ldsm_x4(uint32_t* r, uint32_t addr) {
    asm volatile("ldmatrix.sync.aligned.m8n8.x4.shared.b16 {%0,%1,%2,%3}, [%4];"
                 : "=r"(r[0]), "=r"(r[1]), "=r"(r[2]), "=r"(r[3]) : "r"(addr));
}

__device__ __forceinline__ void mma_f16(float* c, const uint32_t* a, const uint32_t* b) {
    asm volatile(
        "mma.sync.aligned.m16n8k16.row.col.f32.f16.f16.f32 "
        "{%0,%1,%2,%3}, {%4,%5,%6,%7}, {%8,%9}, {%0,%1,%2,%3};"
        : "+f"(c[0]), "+f"(c[1]), "+f"(c[2]), "+f"(c[3])
        : "r"(a[0]), "r"(a[1]), "r"(a[2]), "r"(a[3]), "r"(b[0]), "r"(b[1]));
}

// fast exp (full-rate FFMA path)
__device__ __forceinline__ float fexp(float x)
{
    float t = fmaxf(x * 1.44269504f, -125.0f);
    float fi = t + 12582912.f;
    int   i = __float_as_int(fi);
    float fr = t - (fi - 12582912.f);
    float y = fr * 0.69314718f;
    float p = fmaf(y, 0.25f, 1.f);
    p = fmaf(y * p, 0.33333333f, 1.f);
    p = fmaf(y * p, 0.5f, 1.f);
    p = fmaf(y, p, 1.f);
    return __int_as_float((i + (127 - 0x4B400000)) << 23) * p;
}

// ---------------- fp32→fp16 convert (8 elems/thread) -------------------------
__global__ void f2h_vec(const float* __restrict__ in, __half* __restrict__ out, long n)
{
    long i = ((long)blockIdx.x * blockDim.x + threadIdx.x) * 8;
    if (i >= n) return;
    float4 a = *(const float4*)(in + i);
    float4 b = *(const float4*)(in + i + 4);
    uint4 u;
    u.x = h2bits(a.x, a.y); u.y = h2bits(a.z, a.w);
    u.z = h2bits(b.x, b.y); u.w = h2bits(b.z, b.w);
    *(uint4*)(out + i) = u;
}

// ---------------- cp.async fp16 logits GEMM (4 stages, R11-proven) ----------
#define LG_STAGES 4
#define LG_SMEM (LG_STAGES * 16384)

__global__ __launch_bounds__(256, 2) void gemm_lg(
    const __half* __restrict__ A16, const __half* __restrict__ W16,
    const float* __restrict__ bias, float* __restrict__ C,
    float* __restrict__ rsum)
{
    extern __shared__ char smem[];
    const uint32_t sb = smem_u32(smem);
    const int N = V, K = Hd;

    const int t = threadIdx.x;
    const int lane = t & 31;
    const int wid = t >> 5;
    const int wm = wid >> 2;
    const int wn = wid & 3;
    const int g = lane >> 2;
    const int q = lane & 3;

    const int m0 = blockIdx.y * 128;
    const int n0 = blockIdx.x * 128;

    const int lrow = t >> 2;
    const int lc16 = (t & 3) * 16;
    const int lc8  = (t & 3) * 8;

    float acc[4][4][4];
    #pragma unroll
    for (int i = 0; i < 4; i++)
        #pragma unroll
        for (int j = 0; j < 4; j++)
            #pragma unroll
            for (int v = 0; v < 4; v++) acc[i][j][v] = 0.f;

    auto issue_stage = [&](int s, int c) {
        const int k0 = c * 32;
        const uint32_t Ab = sb + s * 16384;
        const uint32_t Bb = Ab + 8192;
        #pragma unroll
        for (int i = 0; i < 2; i++) {
            int row = lrow + i * 64;
            const __half* src = A16 + (long)(m0 + row) * K + k0 + lc8;
            uint32_t dst = Ab + SWZ64((uint32_t)(row * 64 + lc16));
            asm volatile("cp.async.cg.shared.global [%0], [%1], 16;" :: "r"(dst), "l"(src));
        }
        #pragma unroll
        for (int i = 0; i < 2; i++) {
            int row = lrow + i * 64;
            int n = n0 + row;
            const __half* src = W16 + (long)n * K + k0 + lc8;
            uint32_t dst = Bb + SWZ64((uint32_t)(row * 64 + lc16));
            int bytes = (n < N) ? 16 : 0;
            asm volatile("cp.async.cg.shared.global [%0], [%1], 16, %2;"
                         :: "r"(dst), "l"(src), "r"(bytes));
        }
        asm volatile("cp.async.commit_group;" ::: "memory");
    };

    const int a_row = lane & 15;
    const int a_cb = (lane >> 4) << 4;
    const int b_row = (lane & 7) + ((lane >> 4) << 3);
    const int b_cb = ((lane >> 3) & 1) << 4;

    auto compute = [&](int s) {
        const uint32_t Ab = sb + s * 16384;
        const uint32_t Bb = Ab + 8192;
        #pragma unroll
        for (int ks = 0; ks < 2; ks++) {
            uint32_t af[4][4], bf[2][4];
            #pragma unroll
            for (int mt = 0; mt < 4; mt++) {
                int r = wm * 64 + mt * 16 + a_row;
                ldsm_x4(af[mt], Ab + SWZ64((uint32_t)(r * 64 + ks * 32 + a_cb)));
            }
            #pragma unroll
            for (int np = 0; np < 2; np++) {
                int r = wn * 32 + np * 16 + b_row;
                ldsm_x4(bf[np], Bb + SWZ64((uint32_t)(r * 64 + ks * 32 + b_cb)));
            }
            #pragma unroll
            for (int mt = 0; mt < 4; mt++)
                #pragma unroll
                for (int nt = 0; nt < 4; nt++)
                    mma_f16(acc[mt][nt], af[mt], &bf[nt >> 1][(nt & 1) * 2]);
        }
    };

    const int NCH = K / 32;
    issue_stage(0, 0); issue_stage(1, 1); issue_stage(2, 2);
    for (int c = 0; c < NCH; c++) {
        asm volatile("cp.async.wait_group 2;" ::: "memory");
        __syncthreads();
        compute(c & 3);
        if (c + 3 < NCH) issue_stage((c + 3) & 3, c + 3);
        else asm volatile("cp.async.commit_group;" ::: "memory");
    }

    // ---- epilogue: bias + store + bare exp-sum ----
    float se[4][2];
    #pragma unroll
    for (int mt = 0; mt < 4; mt++) { se[mt][0] = 0.f; se[mt][1] = 0.f; }
    #pragma unroll
    for (int mt = 0; mt < 4; mt++) {
        int row = m0 + wm * 64 + mt * 16 + g;
        #pragma unroll
        for (int nt = 0; nt < 4; nt++) {
            int col = n0 + wn * 32 + nt * 8 + 2 * q;
            float b0 = (col < N) ? bias[col] : 0.f;
            float b1 = (col + 1 < N) ? bias[col + 1] : 0.f;
            float v0 = acc[mt][nt][0] + b0, v1 = acc[mt][nt][1] + b1;
            float v2 = acc[mt][nt][2] + b0, v3 = acc[mt][nt][3] + b1;
            if (col < N)     { C[(long)row * N + col]           = v0; se[mt][0] += fexp(v0); }
            if (col + 1 < N) { C[(long)row * N + col + 1]       = v1; se[mt][0] += fexp(v1); }
            if (col < N)     { C[(long)(row + 8) * N + col]     = v2; se[mt][1] += fexp(v2); }
            if (col + 1 < N) { C[(long)(row + 8) * N + col + 1] = v3; se[mt][1] += fexp(v3); }
        }
    }
    float* reds = (float*)smem;
    __syncthreads();
    #pragma unroll
    for (int mt = 0; mt < 4; mt++) {
        #pragma unroll
        for (int half = 0; half < 2; half++) {
            float sv = se[mt][half];
            sv += __shfl_xor_sync(0xffffffff, sv, 1);
            sv += __shfl_xor_sync(0xffffffff, sv, 2);
            if (q == 0) {
                int rloc = wm * 64 + mt * 16 + g + half * 8;
                reds[wn * 128 + rloc] = sv;
            }
        }
    }
    __syncthreads();
    if (t < 128) {
        float sm = reds[t] + reds[128 + t] + reds[256 + t] + reds[384 + t];
        rsum[(long)(m0 + t) * NTV + blockIdx.x] = sm;
    }
}

// ---------------- cp.async fp16 small GEMM (partials, split-K, concat) ------
// C_part[z][256,N] = concat_K(A1,A2) @ W16^T. All fp16 inputs. K chunks mult 32.
#define SC_SMEM 65536

template<int CONCAT>
__global__ __launch_bounds__(256, 2) void gemm_sc(
    const __half* __restrict__ A1, const __half* __restrict__ A2, int KA1,
    const __half* __restrict__ W16, float* __restrict__ C,
    int N, int K, int chunkK)
{
    extern __shared__ char smem[];
    const uint32_t sb = smem_u32(smem);

    const int t = threadIdx.x;
    const int lane = t & 31;
    const int wid = t >> 5;
    const int wm = wid >> 2;
    const int wn = wid & 3;
    const int g = lane >> 2;
    const int q = lane & 3;

    const int m0 = blockIdx.y * 128;
    const int n0 = blockIdx.x * 128;
    const int kstart = blockIdx.z * chunkK;
    const int kend = min(kstart + chunkK, K);
    const int KA2 = K - KA1;

    const int lrow = t >> 2;
    const int lc16 = (t & 3) * 16;
    const int lc8  = (t & 3) * 8;

    float acc[4][4][4];
    #pragma unroll
    for (int i = 0; i < 4; i++)
        #pragma unroll
        for (int j = 0; j < 4; j++)
            #pragma unroll
            for (int v = 0; v < 4; v++) acc[i][j][v] = 0.f;

    auto issue_stage = [&](int s, int c) {
        const int k0 = kstart + c * 32;
        const uint32_t Ab = sb + s * 16384;
        const uint32_t Bb = Ab + 8192;
        #pragma unroll
        for (int i = 0; i < 2; i++) {
            int row = lrow + i * 64;
            int m = m0 + row;
            int k = k0 + lc8;
            const __half* src;
            if (CONCAT && k >= KA1) src = A2 + (long)m * KA2 + (k - KA1);
            else                    src = A1 + (long)m * (CONCAT ? KA1 : K) + k;
            uint32_t dst = Ab + SWZ64((uint32_t)(row * 64 + lc16));
            asm volatile("cp.async.cg.shared.global [%0], [%1], 16;" :: "r"(dst), "l"(src));
        }
        #pragma unroll
        for (int i = 0; i < 2; i++) {
            int row = lrow + i * 64;
            int n = n0 + row;
            const __half* src = W16 + (long)n * K + k0 + lc8;
            uint32_t dst = Bb + SWZ64((uint32_t)(row * 64 + lc16));
            int bytes = (n < N) ? 16 : 0;
            asm volatile("cp.async.cg.shared.global [%0], [%1], 16, %2;"
                         :: "r"(dst), "l"(src), "r"(bytes));
        }
        asm volatile("cp.async.commit_group;" ::: "memory");
    };

    const int a_row = lane & 15;
    const int a_cb = (lane >> 4) << 4;
    const int b_row = (lane & 7) + ((lane >> 4) << 3);
    const int b_cb = ((lane >> 3) & 1) << 4;

    auto compute = [&](int s) {
        const uint32_t Ab = sb + s * 16384;
        const uint32_t Bb = Ab + 8192;
        #pragma unroll
        for (int ks = 0; ks < 2; ks++) {
            uint32_t af[4][4], bf[2][4];
            #pragma unroll
            for (int mt = 0; mt < 4; mt++) {
                int r = wm * 64 + mt * 16 + a_row;
                ldsm_x4(af[mt], Ab + SWZ64((uint32_t)(r * 64 + ks * 32 + a_cb)));
            }
            #pragma unroll
            for (int np = 0; np < 2; np++) {
                int r = wn * 32 + np * 16 + b_row;
                ldsm_x4(bf[np], Bb + SWZ64((uint32_t)(r * 64 + ks * 32 + b_cb)));
            }
            #pragma unroll
            for (int mt = 0; mt < 4; mt++)
                #pragma unroll
                for (int nt = 0; nt < 4; nt++)
                    mma_f16(acc[mt][nt], af[mt], &bf[nt >> 1][(nt & 1) * 2]);
        }
    };

    const int NCH = (kend - kstart) / 32;
    issue_stage(0, 0); issue_stage(1, 1); issue_stage(2, 2);
    for (int c = 0; c < NCH; c++) {
        asm volatile("cp.async.wait_group 2;" ::: "memory");
        __syncthreads();
        compute(c & 3);
        if (c + 3 < NCH) issue_stage((c + 3) & 3, c + 3);
        else asm volatile("cp.async.commit_group;" ::: "memory");
    }

    float* Cw = C + (long)blockIdx.z * 256 * N;
    #pragma unroll
    for (int mt = 0; mt < 4; mt++) {
        int row = m0 + wm * 64 + mt * 16 + g;
        #pragma unroll
        for (int nt = 0; nt < 4; nt++) {
            int col = n0 + wn * 32 + nt * 8 + 2 * q;
            if (col < N)     Cw[(long)row * N + col]           = acc[mt][nt][0];
            if (col + 1 < N) Cw[(long)row * N + col + 1]       = acc[mt][nt][1];
            if (col < N)     Cw[(long)(row + 8) * N + col]     = acc[mt][nt][2];
            if (col + 1 < N) Cw[(long)(row + 8) * N + col + 1] = acc[mt][nt][3];
        }
    }
}

// ---------------- fp32 tensor-core GEMM (scores + NN; R9 engine) -------------
#define GH_SMEM 65536

template<int TRANSB, int CONCAT>
__global__ __launch_bounds__(256, 1) void gemm_h16(
    const float* __restrict__ A1, const float* __restrict__ A2, int KA1,
    const float* __restrict__ W,
    float* __restrict__ C, int N, int K, int chunkK)
{
    extern __shared__ char smem[];
    const uint32_t sb = smem_u32(smem);

    const int t = threadIdx.x;
    const int lane = t & 31;
    const int wid = t >> 5;
    const int wm = wid >> 2;
    const int wn = wid & 3;
    const int g = lane >> 2;
    const int q = lane & 3;

    const int m0 = blockIdx.y * 128;
    const int n0 = blockIdx.x * 128;
    const int kstart = blockIdx.z * chunkK;
    const int kend = min(kstart + chunkK, K);
    const int KA2 = K - KA1;

    const int arow = t >> 4;
    const int acol = (t & 15) * 4;

    float4 ra[8], rb[8];
    float4 rba[4], rbb[4];

    float acc[4][4][4];
    #pragma unroll
    for (int i = 0; i < 4; i++)
        #pragma unroll
        for (int j = 0; j < 4; j++)
            #pragma unroll
            for (int v = 0; v < 4; v++) acc[i][j][v] = 0.f;

    auto loadA = [&](int k0) {
        #pragma unroll
        for (int i = 0; i < 8; i++) {
            int m = m0 + arow + 16 * i;
            int k = k0 + acol;
            ra[i] = make_float4(0.f, 0.f, 0.f, 0.f);
            if (k < kend) {
                if constexpr (CONCAT) {
                    if (k < KA1) ra[i] = *(const float4*)&A1[(long)m * KA1 + k];
                    else         ra[i] = *(const float4*)&A2[(long)m * KA2 + (k - KA1)];
                } else {
                    ra[i] = *(const float4*)&A1[(long)m * K + k];
                }
            }
        }
    };
    auto loadB = [&](int k0) {
        if (TRANSB) {
            #pragma unroll
            for (int i = 0; i < 8; i++) {
                int n = n0 + arow + 16 * i;
                int k = k0 + acol;
                rb[i] = make_float4(0.f, 0.f, 0.f, 0.f);
                if (n < N && k < kend) rb[i] = *(const float4*)&W[(long)n * K + k];
            }
        } else {
            #pragma unroll
            for (int i = 0; i < 4; i++) {
                int cell = t + i * 256;
                int kp = cell >> 5;
                int nq = cell & 31;
                int k = k0 + 2 * kp;
                int n = n0 + nq * 4;
                rba[i] = make_float4(0.f, 0.f, 0.f, 0.f);
                rbb[i] = make_float4(0.f, 0.f, 0.f, 0.f);
                if (k < kend && n < N) {
                    rba[i] = *(const float4*)&W[(long)k * N + n];
                    if (k + 1 < kend) rbb[i] = *(const float4*)&W[(long)(k + 1) * N + n];
                }
            }
        }
    };
    auto storeAB = [&](int s) {
        char* Ab = smem + s * 32768;
        char* Bb = smem + s * 32768 + 16384;
        #pragma unroll
        for (int i = 0; i < 8; i++) {
            int row = arow + 16 * i;
            uint32_t off = SWZ128((uint32_t)(row * 128 + acol * 2));
            *(uint2*)(Ab + off) = make_uint2(h2bits(ra[i].x, ra[i].y), h2bits(ra[i].z, ra[i].w));
        }
        if (TRANSB) {
            #pragma unroll
            for (int i = 0; i < 8; i++) {
                int row = arow + 16 * i;
                uint32_t off = SWZ128((uint32_t)(row * 128 + acol * 2));
                *(uint2*)(Bb + off) = make_uint2(h2bits(rb[i].x, rb[i].y), h2bits(rb[i].z, rb[i].w));
            }
        } else {
            #pragma unroll
            for (int i = 0; i < 4; i++) {
                int cell = t + i * 256;
                int kp = cell >> 5;
                int nq = cell & 31;
                const float* fa = (const float*)&rba[i];
                const float* fb = (const float*)&rbb[i];
                #pragma unroll
                for (int j = 0; j < 4; j++) {
                    int row = nq * 4 + j;
                    uint32_t off = SWZ128((uint32_t)(row * 128 + kp * 4));
                    *(uint32_t*)(Bb + off) = h2bits(fa[j], fb[j]);
                }
            }
        }
    };

    const int a_row = lane & 15;
    const int a_cb = (lane >> 4) << 4;
    const int b_row = (lane & 7) + ((lane >> 4) << 3);
    const int b_cb = ((lane >> 3) & 1) << 4;

    auto compute = [&](int s) {
        const uint32_t Ab = sb + s * 32768;
        const uint32_t Bb = Ab + 16384;
        #pragma unroll
        for (int ks = 0; ks < 4; ks++) {
            uint32_t af[4][4], bf[2][4];
            #pragma unroll
            for (int mt = 0; mt < 4; mt++) {
                int r = wm * 64 + mt * 16 + a_row;
                ldsm_x4(af[mt], Ab + SWZ128((uint32_t)(r * 128 + ks * 32 + a_cb)));
            }
            #pragma unroll
            for (int np = 0; np < 2; np++) {
                int r = wn * 32 + np * 16 + b_row;
                ldsm_x4(bf[np], Bb + SWZ128((uint32_t)(r * 128 + ks * 32 + b_cb)));
            }
            #pragma unroll
            for (int mt = 0; mt < 4; mt++)
                #pragma unroll
                for (int nt = 0; nt < 4; nt++)
                    mma_f16(acc[mt][nt], af[mt], &bf[nt >> 1][(nt & 1) * 2]);
        }
    };

    const int ntiles = (kend - kstart + 63) / 64;

    loadA(kstart); loadB(kstart);
    storeAB(0);
    __syncthreads();
    for (int c = 1; c < ntiles; c++) {
        loadA(kstart + c * 64); loadB(kstart + c * 64);
        compute((c - 1) & 1);
        storeAB(c & 1);
        __syncthreads();
    }
    compute((ntiles - 1) & 1);

    float* Cw = C + (long)blockIdx.z * 256 * N;
    #pragma unroll
    for (int mt = 0; mt < 4; mt++) {
        int row = m0 + wm * 64 + mt * 16 + g;
        #pragma unroll
        for (int nt = 0; nt < 4; nt++) {
            int col = n0 + wn * 32 + nt * 8 + 2 * q;
            if (col < N)     Cw[(long)row * N + col]           = acc[mt][nt][0];
            if (col + 1 < N) Cw[(long)row * N + col + 1]       = acc[mt][nt][1];
            if (col < N)     Cw[(long)(row + 8) * N + col]     = acc[mt][nt][2];
            if (col + 1 < N) Cw[(long)(row + 8) * N + col + 1] = acc[mt][nt][3];
        }
    }
}

// ---------------- split-K reduce (+bias, +relu, optional fp16 copy) ---------
__global__ void reduce_bias(const float* __restrict__ part, const float* __restrict__ bias,
                            float* __restrict__ out, __half* __restrict__ out16,
                            int MN, int N, int SK, int relu)
{
    int idx = blockIdx.x * blockDim.x + threadIdx.x;
    if (idx >= MN) return;
    float s = 0.f;
    for (int c = 0; c < SK; c++) s += part[(long)c * MN + idx];
    if (bias) s += bias[idx % N];
    if (relu) s = fmaxf(s, 0.f);
    out[idx] = s;
    if (out16) out16[idx] = __float2half_rn(s);
}

// ---------------- fused GRU: reduce (SK=3 each) + gates + dual h write ------
__global__ void gru_fuse(const float* __restrict__ part, const float* __restrict__ hidden,
                         const float* __restrict__ bih, const float* __restrict__ bhh,
                         float* __restrict__ h_new, __half* __restrict__ h16)
{
    int idx = blockIdx.x * blockDim.x + threadIdx.x;
    if (idx >= B * Hd) return;
    int b = idx / Hd, j = idx - b * Hd;
    const long NN = 3 * Hd;
    const long MN = (long)B * NN;
    const float* giA = part;            // [3][B][3H]
    const float* ghA = part + 3 * MN;   // [3][B][3H]
    long base = (long)b * NN + j;

    float ir = bih[j], iz = bih[j + Hd], in_ = bih[j + 2 * Hd];
    float hr = bhh[j], hz = bhh[j + Hd], hn = bhh[j + 2 * Hd];
    #pragma unroll
    for (int c = 0; c < 3; c++) {
        ir  += giA[c * MN + base];
        iz  += giA[c * MN + base + Hd];
        in_ += giA[c * MN + base + 2 * Hd];
        hr  += ghA[c * MN + base];
        hz  += ghA[c * MN + base + Hd];
        hn  += ghA[c * MN + base + 2 * Hd];
    }

    float r = 1.f / (1.f + expf(-(ir + hr)));
    float z = 1.f / (1.f + expf(-(iz + hz)));
    float nn = tanhf(in_ + r * hn);
    float h = (1.f - z) * nn + z * hidden[idx];
    h_new[idx] = h;
    h16[idx] = __float2half_rn(h);
}

// ---------------- warp-per-row softmax (L=400) -------------------------------
__global__ void softmax_warp(const float* __restrict__ in, float* __restrict__ out, int n)
{
    int w = (blockIdx.x * blockDim.x + threadIdx.x) >> 5;
    int lid = threadIdx.x & 31;
    if (w >= B) return;
    const float* x = in + (long)w * n;
    float* y = out + (long)w * n;

    float m = -1e30f;
    for (int i = lid; i < n; i += 32) m = fmaxf(m, x[i]);
    #pragma unroll
    for (int o = 16; o > 0; o >>= 1) m = fmaxf(m, __shfl_xor_sync(0xffffffff, m, o));
    float s = 0.f;
    for (int i = lid; i < n; i += 32) s += fexp(x[i] - m);
    #pragma unroll
    for (int o = 16; o > 0; o >>= 1) s += __shfl_xor_sync(0xffffffff, s, o);
    float inv = 1.f / s;
    for (int i = lid; i < n; i += 32) y[i] = fexp(x[i] - m) * inv;
}

// ---------------- merged lse + subtract: one block per row -------------------
__global__ void logp_finalize(float* __restrict__ logp, const float* __restrict__ rsum)
{
    int row = blockIdx.x;
    int t = threadIdx.x;   // 1024
    float s = 0.f;
    for (int tile = t; tile < NTV; tile += 1024) s += rsum[(long)row * NTV + tile];
    #pragma unroll
    for (int o = 16; o > 0; o >>= 1) s += __shfl_xor_sync(0xffffffff, s, o);
    __shared__ float ss[32];
    __shared__ float lse_s;
    if ((t & 31) == 0) ss[t >> 5] = s;
    __syncthreads();
    if (t == 0) {
        float S = 0.f;
        #pragma unroll
        for (int w = 0; w < 32; w++) S += ss[w];
        lse_s = logf(S);
    }
    __syncthreads();
    float l = lse_s;
    for (int col = t; col < V; col += 1024) logp[(long)row * V + col] -= l;
}

// ---------------- launch -----------------------------------------------------
extern "C" void kernel_launch(void* const* d_in, const int* in_sizes, int n_in,
                              void* d_out, int out_size)
{
    const float* embedded = (const float*)d_in[0];
    const float* hidden   = (const float*)d_in[1];
    const float* enc      = (const float*)d_in[2];
    const float* attn_W   = (const float*)d_in[3];
    const float* attn_b   = (const float*)d_in[4];
    const float* comb_W   = (const float*)d_in[5];
    const float* comb_b   = (const float*)d_in[6];
    const float* gru_Wih  = (const float*)d_in[7];
    const float* gru_Whh  = (const float*)d_in[8];
    const float* gru_bih  = (const float*)d_in[9];
    const float* gru_bhh  = (const float*)d_in[10];
    const float* out_W    = (const float*)d_in[11];
    const float* out_b    = (const float*)d_in[12];

    float* out = (float*)d_out;
    float* out_logp = out;
    float* out_h    = out + OUT_H;
    float* out_aw   = out + OUT_AW;

    float *scores, *attn, *o, *part, *rsum;
    __half *w16, *h16, *h16in, *x16, *attn16, *o16, *whh16, *wih16, *combW16;
    cudaGetSymbolAddress((void**)&scores, g_scores);
    cudaGetSymbolAddress((void**)&attn, g_attn);
    cudaGetSymbolAddress((void**)&o, g_o);
    cudaGetSymbolAddress((void**)&part, g_part);
    cudaGetSymbolAddress((void**)&rsum, g_rsum);
    cudaGetSymbolAddress((void**)&w16, g_w16);
    cudaGetSymbolAddress((void**)&h16, g_h16);
    cudaGetSymbolAddress((void**)&h16in, g_h16in);
    cudaGetSymbolAddress((void**)&x16, g_x16);
    cudaGetSymbolAddress((void**)&attn16, g_attn16);
    cudaGetSymbolAddress((void**)&o16, g_o16);
    cudaGetSymbolAddress((void**)&whh16, g_whh16);
    cudaGetSymbolAddress((void**)&wih16, g_wih16);
    cudaGetSymbolAddress((void**)&combW16, g_combW16);

    static cudaStream_t sW = nullptr, sG = nullptr;
    static cudaEvent_t evFork, evPre, evSmall, evW, evG;
    if (sW == nullptr) {
        cudaStreamCreateWithFlags(&sW, cudaStreamNonBlocking);
        cudaStreamCreateWithFlags(&sG, cudaStreamNonBlocking);
        cudaEventCreateWithFlags(&evFork, cudaEventDisableTiming);
        cudaEventCreateWithFlags(&evPre, cudaEventDisableTiming);
        cudaEventCreateWithFlags(&evSmall, cudaEventDisableTiming);
        cudaEventCreateWithFlags(&evW, cudaEventDisableTiming);
        cudaEventCreateWithFlags(&evG, cudaEventDisableTiming);
    }

    cudaFuncSetAttribute((const void*)gemm_h16<1, 1>, cudaFuncAttributeMaxDynamicSharedMemorySize, GH_SMEM);
    cudaFuncSetAttribute((const void*)gemm_h16<0, 0>, cudaFuncAttributeMaxDynamicSharedMemorySize, GH_SMEM);
    cudaFuncSetAttribute((const void*)gemm_sc<0>, cudaFuncAttributeMaxDynamicSharedMemorySize, SC_SMEM);
    cudaFuncSetAttribute((const void*)gemm_sc<1>, cudaFuncAttributeMaxDynamicSharedMemorySize, SC_SMEM);
    cudaFuncSetAttribute((const void*)gemm_lg, cudaFuncAttributeMaxDynamicSharedMemorySize, LG_SMEM);

    const long MN3 = (long)B * 3 * Hd;

    // ---- fork ----
    cudaEventRecord(evFork, 0);

    // Conversion stream: gh deps first, then chain deps, then the big out_W.
    cudaStreamWaitEvent(sW, evFork, 0);
    f2h_vec<<<(B * Hd / 8 + 255) / 256, 256, 0, sW>>>(hidden, h16in, B * Hd);
    f2h_vec<<<(3 * Hd * Hd / 8 + 255) / 256, 256, 0, sW>>>(gru_Whh, whh16, 3L * Hd * Hd);
    cudaEventRecord(evPre, sW);
    f2h_vec<<<(B * Hd / 8 + 255) / 256, 256, 0, sW>>>(embedded, x16, B * Hd);
    f2h_vec<<<(3 * Hd * Hd / 8 + 255) / 256, 256, 0, sW>>>(gru_Wih, wih16, 3L * Hd * Hd);
    f2h_vec<<<(Hd * 2 * Hd / 8 + 255) / 256, 256, 0, sW>>>(comb_W, combW16, (long)Hd * 2 * Hd);
    cudaEventRecord(evSmall, sW);
    f2h_vec<<<(int)(((long)V * Hd / 8 + 255) / 256), 256, 0, sW>>>(out_W, w16, (long)V * Hd);
    cudaEventRecord(evW, sW);

    // gh = hidden @ Whh^T on side stream (SK=3, region [3MN,6MN))
    cudaStreamWaitEvent(sG, evPre, 0);
    gemm_sc<0><<<dim3(24, 2, 3), 256, SC_SMEM, sG>>>(h16in, nullptr, Hd, whh16,
                                                     part + 3 * MN3, 3 * Hd, Hd, 352);
    cudaEventRecord(evG, sG);

    // ---- main chain ----
    // 1. scores = [x|h] @ attn_W^T (+attn_b), split-K=8 (fp32 engine)
    gemm_h16<1, 1><<<dim3(4, 2, 8), 256, GH_SMEM>>>(embedded, hidden, Hd, attn_W,
                                                    part, L, 2 * Hd, 256);
    reduce_bias<<<(B * L + 255) / 256, 256>>>(part, attn_b, scores, nullptr, B * L, L, 8, 0);

    // 2. attn_weights = softmax(scores) -> out_aw
    softmax_warp<<<32, 256>>>(scores, out_aw, L);

    // 3. attn_applied = attn_weights @ enc (NN, fp32 engine), split-K=4
    gemm_h16<0, 0><<<dim3(8, 2, 4), 256, GH_SMEM>>>(out_aw, nullptr, L, enc,
                                                    part, Hd, L, 128);
    reduce_bias<<<(B * Hd + 255) / 256, 256>>>(part, nullptr, attn, attn16, B * Hd, Hd, 4, 0);

    // 4. o = relu([x16|attn16] @ combW16^T + comb_b), cp.async engine, SK=8
    cudaStreamWaitEvent(0, evSmall, 0);
    gemm_sc<1><<<dim3(8, 2, 8), 256, SC_SMEM>>>(x16, attn16, Hd, combW16,
                                                part, Hd, 2 * Hd, 256);
    reduce_bias<<<(B * Hd + 255) / 256, 256>>>(part, comb_b, o, o16, B * Hd, Hd, 8, 1);

    // 5. gi = o16 @ wih16^T (SK=3); join gh; fused gates + fp16 h
    gemm_sc<0><<<dim3(24, 2, 3), 256, SC_SMEM>>>(o16, nullptr, Hd, wih16,
                                                 part, 3 * Hd, Hd, 352);
    cudaStreamWaitEvent(0, evG, 0);
    gru_fuse<<<(B * Hd + 255) / 256, 256>>>(part, hidden, gru_bih, gru_bhh, out_h, h16);

    // 6. join w16; logits -> out_logp (4-stage cp.async, exp-sum fused)
    cudaStreamWaitEvent(0, evW, 0);
    gemm_lg<<<dim3(NTV, 2), 256, LG_SMEM>>>(h16, w16, out_b, out_logp, rsum);

    // 7. merged lse + in-place subtract (block per row)
    logp_finalize<<<B, 1024>>>(out_logp, rsum);
}

// round 14
// speedup vs baseline: 1.1743x; 1.0293x over previous
#include <cuda_runtime.h>
#include <cuda_fp16.h>
#include <math.h>
#include <stdint.h>

// Problem constants
#define B   256
#define Hd  1024
#define L   400
#define LP  416              // L padded to mult of 32
#define V   50257
#define NTV 393              // ceil(V/128)

#define OUT_H    ((long)B * V)
#define OUT_AW   ((long)B * V + (long)B * Hd)

// ---------------- scratch (device globals) ---------------------------------
__device__ float g_attn[B * Hd];
__device__ float g_o[B * Hd];
__device__ float g_part[6L * B * 3 * Hd];     // split-K partials: gi [0,3MN), gh [3MN,6MN)
__device__ float g_rsum[(long)B * NTV];       // [row][tile] exp-sums
__device__ __half g_w16[(long)V * Hd];        // fp16 out_W
__device__ __half g_h16[B * Hd];              // fp16 h_new
__device__ __half g_h16in[B * Hd];            // fp16 hidden (input)
__device__ __half g_x16[B * Hd];              // fp16 embedded
__device__ __half g_attn16[B * Hd];           // fp16 attn_applied
__device__ __half g_o16[B * Hd];              // fp16 o
__device__ __half g_aw16[B * LP];             // fp16 attn weights (padded)
__device__ __half g_whh16[3 * Hd * Hd];
__device__ __half g_wih16[3 * Hd * Hd];
__device__ __half g_combW16[Hd * 2 * Hd];
__device__ __half g_attnW16[L * 2 * Hd];
__device__ __half g_encT16[Hd * LP];          // enc^T fp16, [Hd][LP] zero-padded

// ---------------- helpers ---------------------------------------------------
__device__ __forceinline__ uint32_t smem_u32(const void* p) {
    uint32_t a;
    asm("{ .reg .u64 t; cvta.to.shared.u64 t, %1; cvt.u32.u64 %0, t; }" : "=r"(a) : "l"(p));
    return a;
}

__device__ __forceinline__ uint32_t h2bits(float x, float y) {
    __half2 h = __floats2half2_rn(x, y);
    return *(uint32_t*)&h;
}

#define SWZ64(x)  ((x) ^ (((x) >> 3) & 0x30))

__device__ __forceinline__ void ldsm_x4(uint32_t* r, uint32_t addr) {
    asm volatile("ldmatrix.sync.aligned.m8n8.x4.shared.b16 {%0,%1,%2,%3}, [%4];"
                 : "=r"(r[0]), "=r"(r[1]), "=r"(r[2]), "=r"(r[3]) : "r"(addr));
}

__device__ __forceinline__ void mma_f16(float* c, const uint32_t* a, const uint32_t* b) {
    asm volatile(
        "mma.sync.aligned.m16n8k16.row.col.f32.f16.f16.f32 "
        "{%0,%1,%2,%3}, {%4,%5,%6,%7}, {%8,%9}, {%0,%1,%2,%3};"
        : "+f"(c[0]), "+f"(c[1]), "+f"(c[2]), "+f"(c[3])
        : "r"(a[0]), "r"(a[1]), "r"(a[2]), "r"(a[3]), "r"(b[0]), "r"(b[1]));
}

// fast exp (full-rate FFMA path)
__device__ __forceinline__ float fexp(float x)
{
    float t = fmaxf(x * 1.44269504f, -125.0f);
    float fi = t + 12582912.f;
    int   i = __float_as_int(fi);
    float fr = t - (fi - 12582912.f);
    float y = fr * 0.69314718f;
    float p = fmaf(y, 0.25f, 1.f);
    p = fmaf(y * p, 0.33333333f, 1.f);
    p = fmaf(y * p, 0.5f, 1.f);
    p = fmaf(y, p, 1.f);
    return __int_as_float((i + (127 - 0x4B400000)) << 23) * p;
}

// ---------------- fp32→fp16 convert (8 elems/thread) -------------------------
__global__ void f2h_vec(const float* __restrict__ in, __half* __restrict__ out, long n)
{
    long i = ((long)blockIdx.x * blockDim.x + threadIdx.x) * 8;
    if (i >= n) return;
    float4 a = *(const float4*)(in + i);
    float4 b = *(const float4*)(in + i + 4);
    uint4 u;
    u.x = h2bits(a.x, a.y); u.y = h2bits(a.z, a.w);
    u.z = h2bits(b.x, b.y); u.w = h2bits(b.z, b.w);
    *(uint4*)(out + i) = u;
}

// ---------------- enc transpose+convert: [L,Hd] fp32 -> [Hd,LP] fp16 ---------
__global__ void enc_t16(const float* __restrict__ enc, __half* __restrict__ encT)
{
    __shared__ float tile[32][33];
    int l0 = blockIdx.x * 32;      // 13 blocks -> covers LP=416
    int h0 = blockIdx.y * 32;      // 32 blocks
    int tx = threadIdx.x, ty = threadIdx.y;   // (32, 8)
    #pragma unroll
    for (int i = 0; i < 4; i++) {
        int l = l0 + ty + i * 8;
        tile[ty + i * 8][tx] = (l < L) ? enc[(long)l * Hd + h0 + tx] : 0.f;
    }
    __syncthreads();
    #pragma unroll
    for (int i = 0; i < 4; i++) {
        int h = h0 + ty + i * 8;
        encT[(long)h * LP + l0 + tx] = __float2half_rn(tile[tx][ty + i * 8]);
    }
}

// ---------------- cp.async fp16 logits GEMM (4 stages) ----------------------
#define LG_STAGES 4
#define LG_SMEM (LG_STAGES * 16384)

__global__ __launch_bounds__(256, 2) void gemm_lg(
    const __half* __restrict__ A16, const __half* __restrict__ W16,
    const float* __restrict__ bias, float* __restrict__ C,
    float* __restrict__ rsum)
{
    extern __shared__ char smem[];
    const uint32_t sb = smem_u32(smem);
    const int N = V, K = Hd;

    const int t = threadIdx.x;
    const int lane = t & 31;
    const int wid = t >> 5;
    const int wm = wid >> 2;
    const int wn = wid & 3;
    const int g = lane >> 2;
    const int q = lane & 3;

    const int m0 = blockIdx.y * 128;
    const int n0 = blockIdx.x * 128;

    const int lrow = t >> 2;
    const int lc16 = (t & 3) * 16;
    const int lc8  = (t & 3) * 8;

    float acc[4][4][4];
    #pragma unroll
    for (int i = 0; i < 4; i++)
        #pragma unroll
        for (int j = 0; j < 4; j++)
            #pragma unroll
            for (int v = 0; v < 4; v++) acc[i][j][v] = 0.f;

    auto issue_stage = [&](int s, int c) {
        const int k0 = c * 32;
        const uint32_t Ab = sb + s * 16384;
        const uint32_t Bb = Ab + 8192;
        #pragma unroll
        for (int i = 0; i < 2; i++) {
            int row = lrow + i * 64;
            const __half* src = A16 + (long)(m0 + row) * K + k0 + lc8;
            uint32_t dst = Ab + SWZ64((uint32_t)(row * 64 + lc16));
            asm volatile("cp.async.cg.shared.global [%0], [%1], 16;" :: "r"(dst), "l"(src));
        }
        #pragma unroll
        for (int i = 0; i < 2; i++) {
            int row = lrow + i * 64;
            int n = n0 + row;
            const __half* src = W16 + (long)n * K + k0 + lc8;
            uint32_t dst = Bb + SWZ64((uint32_t)(row * 64 + lc16));
            int bytes = (n < N) ? 16 : 0;
            asm volatile("cp.async.cg.shared.global [%0], [%1], 16, %2;"
                         :: "r"(dst), "l"(src), "r"(bytes));
        }
        asm volatile("cp.async.commit_group;" ::: "memory");
    };

    const int a_row = lane & 15;
    const int a_cb = (lane >> 4) << 4;
    const int b_row = (lane & 7) + ((lane >> 4) << 3);
    const int b_cb = ((lane >> 3) & 1) << 4;

    auto compute = [&](int s) {
        const uint32_t Ab = sb + s * 16384;
        const uint32_t Bb = Ab + 8192;
        #pragma unroll
        for (int ks = 0; ks < 2; ks++) {
            uint32_t af[4][4], bf[2][4];
            #pragma unroll
            for (int mt = 0; mt < 4; mt++) {
                int r = wm * 64 + mt * 16 + a_row;
                ldsm_x4(af[mt], Ab + SWZ64((uint32_t)(r * 64 + ks * 32 + a_cb)));
            }
            #pragma unroll
            for (int np = 0; np < 2; np++) {
                int r = wn * 32 + np * 16 + b_row;
                ldsm_x4(bf[np], Bb + SWZ64((uint32_t)(r * 64 + ks * 32 + b_cb)));
            }
            #pragma unroll
            for (int mt = 0; mt < 4; mt++)
                #pragma unroll
                for (int nt = 0; nt < 4; nt++)
                    mma_f16(acc[mt][nt], af[mt], &bf[nt >> 1][(nt & 1) * 2]);
        }
    };

    const int NCH = K / 32;
    issue_stage(0, 0); issue_stage(1, 1); issue_stage(2, 2);
    for (int c = 0; c < NCH; c++) {
        asm volatile("cp.async.wait_group 2;" ::: "memory");
        __syncthreads();
        compute(c & 3);
        if (c + 3 < NCH) issue_stage((c + 3) & 3, c + 3);
        else asm volatile("cp.async.commit_group;" ::: "memory");
    }

    // ---- epilogue: bias + store + bare exp-sum ----
    float se[4][2];
    #pragma unroll
    for (int mt = 0; mt < 4; mt++) { se[mt][0] = 0.f; se[mt][1] = 0.f; }
    #pragma unroll
    for (int mt = 0; mt < 4; mt++) {
        int row = m0 + wm * 64 + mt * 16 + g;
        #pragma unroll
        for (int nt = 0; nt < 4; nt++) {
            int col = n0 + wn * 32 + nt * 8 + 2 * q;
            float b0 = (col < N) ? bias[col] : 0.f;
            float b1 = (col + 1 < N) ? bias[col + 1] : 0.f;
            float v0 = acc[mt][nt][0] + b0, v1 = acc[mt][nt][1] + b1;
            float v2 = acc[mt][nt][2] + b0, v3 = acc[mt][nt][3] + b1;
            if (col < N)     { C[(long)row * N + col]           = v0; se[mt][0] += fexp(v0); }
            if (col + 1 < N) { C[(long)row * N + col + 1]       = v1; se[mt][0] += fexp(v1); }
            if (col < N)     { C[(long)(row + 8) * N + col]     = v2; se[mt][1] += fexp(v2); }
            if (col + 1 < N) { C[(long)(row + 8) * N + col + 1] = v3; se[mt][1] += fexp(v3); }
        }
    }
    float* reds = (float*)smem;
    __syncthreads();
    #pragma unroll
    for (int mt = 0; mt < 4; mt++) {
        #pragma unroll
        for (int half = 0; half < 2; half++) {
            float sv = se[mt][half];
            sv += __shfl_xor_sync(0xffffffff, sv, 1);
            sv += __shfl_xor_sync(0xffffffff, sv, 2);
            if (q == 0) {
                int rloc = wm * 64 + mt * 16 + g + half * 8;
                reds[wn * 128 + rloc] = sv;
            }
        }
    }
    __syncthreads();
    if (t < 128) {
        float sm = reds[t] + reds[128 + t] + reds[256 + t] + reds[384 + t];
        rsum[(long)(m0 + t) * NTV + blockIdx.x] = sm;
    }
}

// ---------------- cp.async fp16 small GEMM (partials, split-K, concat) ------
#define SC_SMEM 65536

template<int CONCAT>
__global__ __launch_bounds__(256, 2) void gemm_sc(
    const __half* __restrict__ A1, const __half* __restrict__ A2, int KA1,
    const __half* __restrict__ W16, float* __restrict__ C,
    int N, int K, int chunkK)
{
    extern __shared__ char smem[];
    const uint32_t sb = smem_u32(smem);

    const int t = threadIdx.x;
    const int lane = t & 31;
    const int wid = t >> 5;
    const int wm = wid >> 2;
    const int wn = wid & 3;
    const int g = lane >> 2;
    const int q = lane & 3;

    const int m0 = blockIdx.y * 128;
    const int n0 = blockIdx.x * 128;
    const int kstart = blockIdx.z * chunkK;
    const int kend = min(kstart + chunkK, K);
    const int KA2 = K - KA1;

    const int lrow = t >> 2;
    const int lc16 = (t & 3) * 16;
    const int lc8  = (t & 3) * 8;

    float acc[4][4][4];
    #pragma unroll
    for (int i = 0; i < 4; i++)
        #pragma unroll
        for (int j = 0; j < 4; j++)
            #pragma unroll
            for (int v = 0; v < 4; v++) acc[i][j][v] = 0.f;

    auto issue_stage = [&](int s, int c) {
        const int k0 = kstart + c * 32;
        const uint32_t Ab = sb + s * 16384;
        const uint32_t Bb = Ab + 8192;
        #pragma unroll
        for (int i = 0; i < 2; i++) {
            int row = lrow + i * 64;
            int m = m0 + row;
            int k = k0 + lc8;
            const __half* src;
            if (CONCAT && k >= KA1) src = A2 + (long)m * KA2 + (k - KA1);
            else                    src = A1 + (long)m * (CONCAT ? KA1 : K) + k;
            uint32_t dst = Ab + SWZ64((uint32_t)(row * 64 + lc16));
            asm volatile("cp.async.cg.shared.global [%0], [%1], 16;" :: "r"(dst), "l"(src));
        }
        #pragma unroll
        for (int i = 0; i < 2; i++) {
            int row = lrow + i * 64;
            int n = n0 + row;
            const __half* src = W16 + (long)n * K + k0 + lc8;
            uint32_t dst = Bb + SWZ64((uint32_t)(row * 64 + lc16));
            int bytes = (n < N) ? 16 : 0;
            asm volatile("cp.async.cg.shared.global [%0], [%1], 16, %2;"
                         :: "r"(dst), "l"(src), "r"(bytes));
        }
        asm volatile("cp.async.commit_group;" ::: "memory");
    };

    const int a_row = lane & 15;
    const int a_cb = (lane >> 4) << 4;
    const int b_row = (lane & 7) + ((lane >> 4) << 3);
    const int b_cb = ((lane >> 3) & 1) << 4;

    auto compute = [&](int s) {
        const uint32_t Ab = sb + s * 16384;
        const uint32_t Bb = Ab + 8192;
        #pragma unroll
        for (int ks = 0; ks < 2; ks++) {
            uint32_t af[4][4], bf[2][4];
            #pragma unroll
            for (int mt = 0; mt < 4; mt++) {
                int r = wm * 64 + mt * 16 + a_row;
                ldsm_x4(af[mt], Ab + SWZ64((uint32_t)(r * 64 + ks * 32 + a_cb)));
            }
            #pragma unroll
            for (int np = 0; np < 2; np++) {
                int r = wn * 32 + np * 16 + b_row;
                ldsm_x4(bf[np], Bb + SWZ64((uint32_t)(r * 64 + ks * 32 + b_cb)));
            }
            #pragma unroll
            for (int mt = 0; mt < 4; mt++)
                #pragma unroll
                for (int nt = 0; nt < 4; nt++)
                    mma_f16(acc[mt][nt], af[mt], &bf[nt >> 1][(nt & 1) * 2]);
        }
    };

    const int NCH = (kend - kstart) / 32;
    issue_stage(0, 0); issue_stage(1, 1); issue_stage(2, 2);
    for (int c = 0; c < NCH; c++) {
        asm volatile("cp.async.wait_group 2;" ::: "memory");
        __syncthreads();
        compute(c & 3);
        if (c + 3 < NCH) issue_stage((c + 3) & 3, c + 3);
        else asm volatile("cp.async.commit_group;" ::: "memory");
    }

    float* Cw = C + (long)blockIdx.z * 256 * N;
    #pragma unroll
    for (int mt = 0; mt < 4; mt++) {
        int row = m0 + wm * 64 + mt * 16 + g;
        #pragma unroll
        for (int nt = 0; nt < 4; nt++) {
            int col = n0 + wn * 32 + nt * 8 + 2 * q;
            if (col < N)     Cw[(long)row * N + col]           = acc[mt][nt][0];
            if (col + 1 < N) Cw[(long)row * N + col + 1]       = acc[mt][nt][1];
            if (col < N)     Cw[(long)(row + 8) * N + col]     = acc[mt][nt][2];
            if (col + 1 < N) Cw[(long)(row + 8) * N + col + 1] = acc[mt][nt][3];
        }
    }
}

// ---------------- split-K reduce (+bias, +relu, optional fp16 copy) ---------
__global__ void reduce_bias(const float* __restrict__ part, const float* __restrict__ bias,
                            float* __restrict__ out, __half* __restrict__ out16,
                            int MN, int N, int SK, int relu)
{
    int idx = blockIdx.x * blockDim.x + threadIdx.x;
    if (idx >= MN) return;
    float s = 0.f;
    for (int c = 0; c < SK; c++) s += part[(long)c * MN + idx];
    if (bias) s += bias[idx % N];
    if (relu) s = fmaxf(s, 0.f);
    out[idx] = s;
    if (out16) out16[idx] = __float2half_rn(s);
}

// ---------------- fused scores reduce + bias + softmax (block per row) ------
__global__ void softmax_row(const float* __restrict__ part, const float* __restrict__ bias,
                            float* __restrict__ out_aw, __half* __restrict__ aw16)
{
    int row = blockIdx.x;
    int t = threadIdx.x;   // 128
    __shared__ float red[4];

    float v[4];
    int n = 0;
    for (int i = t; i < L; i += 128, n++) {
        float s = bias[i];
        #pragma unroll
        for (int z = 0; z < 8; z++) s += part[(long)z * B * L + (long)row * L + i];
        v[n] = s;
    }
    float m = -1e30f;
    for (int j = 0; j < n; j++) m = fmaxf(m, v[j]);
    #pragma unroll
    for (int o = 16; o > 0; o >>= 1) m = fmaxf(m, __shfl_xor_sync(0xffffffff, m, o));
    if ((t & 31) == 0) red[t >> 5] = m;
    __syncthreads();
    m = fmaxf(fmaxf(red[0], red[1]), fmaxf(red[2], red[3]));

    float s = 0.f;
    for (int j = 0; j < n; j++) { v[j] = fexp(v[j] - m); s += v[j]; }
    #pragma unroll
    for (int o = 16; o > 0; o >>= 1) s += __shfl_xor_sync(0xffffffff, s, o);
    __syncthreads();
    if ((t & 31) == 0) red[t >> 5] = s;
    __syncthreads();
    s = red[0] + red[1] + red[2] + red[3];
    float inv = 1.f / s;
    n = 0;
    for (int i = t; i < L; i += 128, n++) {
        float w = v[n] * inv;
        out_aw[(long)row * L + i] = w;
        aw16[(long)row * LP + i] = __float2half_rn(w);
    }
    for (int i = L + t; i < LP; i += 128) aw16[(long)row * LP + i] = __ushort_as_half(0);
}

// ---------------- fused GRU: reduce (SK=3 each) + gates + dual h write ------
__global__ void gru_fuse(const float* __restrict__ part, const float* __restrict__ hidden,
                         const float* __restrict__ bih, const float* __restrict__ bhh,
                         float* __restrict__ h_new, __half* __restrict__ h16)
{
    int idx = blockIdx.x * blockDim.x + threadIdx.x;
    if (idx >= B * Hd) return;
    int b = idx / Hd, j = idx - b * Hd;
    const long NN = 3 * Hd;
    const long MN = (long)B * NN;
    const float* giA = part;
    const float* ghA = part + 3 * MN;
    long base = (long)b * NN + j;

    float ir = bih[j], iz = bih[j + Hd], in_ = bih[j + 2 * Hd];
    float hr = bhh[j], hz = bhh[j + Hd], hn = bhh[j + 2 * Hd];
    #pragma unroll
    for (int c = 0; c < 3; c++) {
        ir  += giA[c * MN + base];
        iz  += giA[c * MN + base + Hd];
        in_ += giA[c * MN + base + 2 * Hd];
        hr  += ghA[c * MN + base];
        hz  += ghA[c * MN + base + Hd];
        hn  += ghA[c * MN + base + 2 * Hd];
    }

    float r = 1.f / (1.f + expf(-(ir + hr)));
    float z = 1.f / (1.f + expf(-(iz + hz)));
    float nn = tanhf(in_ + r * hn);
    float h = (1.f - z) * nn + z * hidden[idx];
    h_new[idx] = h;
    h16[idx] = __float2half_rn(h);
}

// ---------------- merged lse + subtract: one block per row -------------------
__global__ void logp_finalize(float* __restrict__ logp, const float* __restrict__ rsum)
{
    int row = blockIdx.x;
    int t = threadIdx.x;   // 1024
    float s = 0.f;
    for (int tile = t; tile < NTV; tile += 1024) s += rsum[(long)row * NTV + tile];
    #pragma unroll
    for (int o = 16; o > 0; o >>= 1) s += __shfl_xor_sync(0xffffffff, s, o);
    __shared__ float ss[32];
    __shared__ float lse_s;
    if ((t & 31) == 0) ss[t >> 5] = s;
    __syncthreads();
    if (t == 0) {
        float S = 0.f;
        #pragma unroll
        for (int w = 0; w < 32; w++) S += ss[w];
        lse_s = logf(S);
    }
    __syncthreads();
    float l = lse_s;
    for (int col = t; col < V; col += 1024) logp[(long)row * V + col] -= l;
}

// ---------------- launch -----------------------------------------------------
extern "C" void kernel_launch(void* const* d_in, const int* in_sizes, int n_in,
                              void* d_out, int out_size)
{
    const float* embedded = (const float*)d_in[0];
    const float* hidden   = (const float*)d_in[1];
    const float* enc      = (const float*)d_in[2];
    const float* attn_W   = (const float*)d_in[3];
    const float* attn_b   = (const float*)d_in[4];
    const float* comb_W   = (const float*)d_in[5];
    const float* comb_b   = (const float*)d_in[6];
    const float* gru_Wih  = (const float*)d_in[7];
    const float* gru_Whh  = (const float*)d_in[8];
    const float* gru_bih  = (const float*)d_in[9];
    const float* gru_bhh  = (const float*)d_in[10];
    const float* out_W    = (const float*)d_in[11];
    const float* out_b    = (const float*)d_in[12];

    float* out = (float*)d_out;
    float* out_logp = out;
    float* out_h    = out + OUT_H;
    float* out_aw   = out + OUT_AW;

    float *attn, *o, *part, *rsum;
    __half *w16, *h16, *h16in, *x16, *attn16, *o16, *aw16;
    __half *whh16, *wih16, *combW16, *attnW16, *encT16;
    cudaGetSymbolAddress((void**)&attn, g_attn);
    cudaGetSymbolAddress((void**)&o, g_o);
    cudaGetSymbolAddress((void**)&part, g_part);
    cudaGetSymbolAddress((void**)&rsum, g_rsum);
    cudaGetSymbolAddress((void**)&w16, g_w16);
    cudaGetSymbolAddress((void**)&h16, g_h16);
    cudaGetSymbolAddress((void**)&h16in, g_h16in);
    cudaGetSymbolAddress((void**)&x16, g_x16);
    cudaGetSymbolAddress((void**)&attn16, g_attn16);
    cudaGetSymbolAddress((void**)&o16, g_o16);
    cudaGetSymbolAddress((void**)&aw16, g_aw16);
    cudaGetSymbolAddress((void**)&whh16, g_whh16);
    cudaGetSymbolAddress((void**)&wih16, g_wih16);
    cudaGetSymbolAddress((void**)&combW16, g_combW16);
    cudaGetSymbolAddress((void**)&attnW16, g_attnW16);
    cudaGetSymbolAddress((void**)&encT16, g_encT16);

    static cudaStream_t sW = nullptr, sG = nullptr;
    static cudaEvent_t evFork, evA, evPre, evE, evSmall, evW, evG;
    if (sW == nullptr) {
        cudaStreamCreateWithFlags(&sW, cudaStreamNonBlocking);
        cudaStreamCreateWithFlags(&sG, cudaStreamNonBlocking);
        cudaEventCreateWithFlags(&evFork, cudaEventDisableTiming);
        cudaEventCreateWithFlags(&evA, cudaEventDisableTiming);
        cudaEventCreateWithFlags(&evPre, cudaEventDisableTiming);
        cudaEventCreateWithFlags(&evE, cudaEventDisableTiming);
        cudaEventCreateWithFlags(&evSmall, cudaEventDisableTiming);
        cudaEventCreateWithFlags(&evW, cudaEventDisableTiming);
        cudaEventCreateWithFlags(&evG, cudaEventDisableTiming);
    }

    cudaFuncSetAttribute((const void*)gemm_sc<0>, cudaFuncAttributeMaxDynamicSharedMemorySize, SC_SMEM);
    cudaFuncSetAttribute((const void*)gemm_sc<1>, cudaFuncAttributeMaxDynamicSharedMemorySize, SC_SMEM);
    cudaFuncSetAttribute((const void*)gemm_lg, cudaFuncAttributeMaxDynamicSharedMemorySize, LG_SMEM);

    const long MN3 = (long)B * 3 * Hd;

    // ---- fork ----
    cudaEventRecord(evFork, 0);

    // Conversion stream, ordered by when consumers need them.
    cudaStreamWaitEvent(sW, evFork, 0);
    f2h_vec<<<(B * Hd / 8 + 255) / 256, 256, 0, sW>>>(hidden, h16in, B * Hd);
    f2h_vec<<<(B * Hd / 8 + 255) / 256, 256, 0, sW>>>(embedded, x16, B * Hd);
    f2h_vec<<<(L * 2 * Hd / 8 + 255) / 256, 256, 0, sW>>>(attn_W, attnW16, (long)L * 2 * Hd);
    cudaEventRecord(evA, sW);
    f2h_vec<<<(3 * Hd * Hd / 8 + 255) / 256, 256, 0, sW>>>(gru_Whh, whh16, 3L * Hd * Hd);
    cudaEventRecord(evPre, sW);
    enc_t16<<<dim3(13, 32), dim3(32, 8), 0, sW>>>(enc, encT16);
    cudaEventRecord(evE, sW);
    f2h_vec<<<(3 * Hd * Hd / 8 + 255) / 256, 256, 0, sW>>>(gru_Wih, wih16, 3L * Hd * Hd);
    f2h_vec<<<(Hd * 2 * Hd / 8 + 255) / 256, 256, 0, sW>>>(comb_W, combW16, (long)Hd * 2 * Hd);
    cudaEventRecord(evSmall, sW);
    f2h_vec<<<(int)(((long)V * Hd / 8 + 255) / 256), 256, 0, sW>>>(out_W, w16, (long)V * Hd);
    cudaEventRecord(evW, sW);

    // gh = hidden @ Whh^T on side stream (SK=3, region [3MN,6MN))
    cudaStreamWaitEvent(sG, evPre, 0);
    gemm_sc<0><<<dim3(24, 2, 3), 256, SC_SMEM, sG>>>(h16in, nullptr, Hd, whh16,
                                                     part + 3 * MN3, 3 * Hd, Hd, 352);
    cudaEventRecord(evG, sG);

    // ---- main chain ----
    // 1. scores partials = [x16|h16in] @ attnW16^T, split-K=8 (fp16 engine)
    cudaStreamWaitEvent(0, evA, 0);
    gemm_sc<1><<<dim3(4, 2, 8), 256, SC_SMEM>>>(x16, h16in, Hd, attnW16,
                                                part, L, 2 * Hd, 256);

    // 2. fused reduce+bias+softmax -> out_aw + aw16 (block per row)
    softmax_row<<<B, 128>>>(part, attn_b, out_aw, aw16);

    // 3. attn_applied = aw @ enc == aw16 @ encT16^T (TN fp16), K=LP, SK=2
    cudaStreamWaitEvent(0, evE, 0);
    gemm_sc<0><<<dim3(8, 2, 2), 256, SC_SMEM>>>(aw16, nullptr, LP, encT16,
                                                part, Hd, LP, 224);
    reduce_bias<<<(B * Hd + 255) / 256, 256>>>(part, nullptr, attn, attn16, B * Hd, Hd, 2, 0);

    // 4. o = relu([x16|attn16] @ combW16^T + comb_b), SK=8
    cudaStreamWaitEvent(0, evSmall, 0);
    gemm_sc<1><<<dim3(8, 2, 8), 256, SC_SMEM>>>(x16, attn16, Hd, combW16,
                                                part, Hd, 2 * Hd, 256);
    reduce_bias<<<(B * Hd + 255) / 256, 256>>>(part, comb_b, o, o16, B * Hd, Hd, 8, 1);

    // 5. gi = o16 @ wih16^T (SK=3); join gh; fused gates + fp16 h
    gemm_sc<0><<<dim3(24, 2, 3), 256, SC_SMEM>>>(o16, nullptr, Hd, wih16,
                                                 part, 3 * Hd, Hd, 352);
    cudaStreamWaitEvent(0, evG, 0);
    gru_fuse<<<(B * Hd + 255) / 256, 256>>>(part, hidden, gru_bih, gru_bhh, out_h, h16);

    // 6. join w16; logits -> out_logp (4-stage cp.async, exp-sum fused)
    cudaStreamWaitEvent(0, evW, 0);
    gemm_lg<<<dim3(NTV, 2), 256, LG_SMEM>>>(h16, w16, out_b, out_logp, rsum);

    // 7. merged lse + in-place subtract (block per row)
    logp_finalize<<<B, 1024>>>(out_logp, rsum);
}